// round 9
// baseline (speedup 1.0000x reference)
#include <cuda_runtime.h>
#include <cstdint>

#define OUT_CH 16
#define PH 7
#define PW 7
#define SR 2
#define HH 80
#define WW 80
#define PLANE_ELEMS (HH * WW)            // 6400 floats
#define PLANE_BYTES (PLANE_ELEMS * 4)    // 25600 B
#define NPLANE (OUT_CH * PH * PW)        // 784 channels per batch
#define N_ROIS 512
#define NB 4
#define NPLANES_TOTAL (NB * NPLANE)      // 3136
#define TPB 256
#define GRID 592                          // 4 persistent blocks per SM
#define SMEM_DYN (2 * PLANE_BYTES)        // 51200 B: two stages

// scratch (no allocation allowed)
__device__ float g_params[N_ROIS * 4];    // x1, y1, bh, bw
__device__ int   g_perm[N_ROIS];          // rois sorted by batch
__device__ int   g_boff[NB + 1];          // batch list offsets

__device__ __forceinline__ uint32_t smem_u32(const void* p) {
    uint32_t a;
    asm("{ .reg .u64 t; cvta.to.shared.u64 t, %1; cvt.u32.u64 %0, t; }"
        : "=r"(a) : "l"(p));
    return a;
}

__device__ __forceinline__ void mbar_wait(uint32_t mbar, uint32_t parity) {
    uint32_t done;
    asm volatile(
        "{\n\t.reg .pred p;\n\t"
        "mbarrier.try_wait.parity.acquire.cta.shared::cta.b64 p, [%1], %2;\n\t"
        "selp.b32 %0, 1, 0, p;\n\t}"
        : "=r"(done) : "r"(mbar), "r"(parity) : "memory");
    if (!done) {
        asm volatile(
            "{\n\t.reg .pred P1;\n\t"
            "WAIT_LOOP_%=:\n\t"
            "mbarrier.try_wait.parity.acquire.cta.shared::cta.b64 P1, [%0], %1, 0x989680;\n\t"
            "@P1 bra.uni WAIT_DONE_%=;\n\t"
            "bra.uni WAIT_LOOP_%=;\n\t"
            "WAIT_DONE_%=:\n\t}"
            :: "r"(mbar), "r"(parity) : "memory");
    }
}

// ── Kernel A: per-roi params + counting sort by batch ───────────────────
__global__ void __launch_bounds__(N_ROIS)
roi_prep_kernel(const float* __restrict__ rois) {
    __shared__ int s_cnt[NB];
    __shared__ int s_base[NB];
    const int t = threadIdx.x;
    if (t < NB) s_cnt[t] = 0;
    __syncthreads();

    const float* r = rois + (size_t)t * 5;
    const int   b  = (int)r[0];
    const float x1 = r[1] * (float)WW;
    const float y1 = r[2] * (float)HH;
    const float x2 = r[3] * (float)WW;
    const float y2 = r[4] * (float)HH;
    float* p = g_params + (size_t)t * 4;
    p[0] = x1;
    p[1] = y1;
    p[2] = fmaxf(y2 - y1, 0.1f) * (1.0f / (float)PH);
    p[3] = fmaxf(x2 - x1, 0.1f) * (1.0f / (float)PW);

    const int rank = atomicAdd(&s_cnt[b], 1);
    __syncthreads();
    if (t == 0) {
        int acc = 0;
        for (int i = 0; i < NB; i++) { s_base[i] = acc; g_boff[i] = acc; acc += s_cnt[i]; }
        g_boff[NB] = acc;
    }
    __syncthreads();
    g_perm[s_base[b] + rank] = t;
}

// ── Kernel B: persistent blocks, double-buffered TMA pipeline ───────────
__global__ void __launch_bounds__(TPB)
psroi_align_kernel(const float* __restrict__ feat,
                   float* __restrict__ out) {
    extern __shared__ __align__(16) float s_buf[];      // [2][PLANE_ELEMS]
    __shared__ alignas(8) uint64_t s_mbar[2];

    const int tid = threadIdx.x;
    const int bid = blockIdx.x;
    const uint32_t mb0 = smem_u32(&s_mbar[0]);
    const uint32_t mb1 = smem_u32(&s_mbar[1]);

    if (tid == 0) {
        asm volatile("mbarrier.init.shared.b64 [%0], 1;" :: "r"(mb0) : "memory");
        asm volatile("mbarrier.init.shared.b64 [%0], 1;" :: "r"(mb1) : "memory");
        asm volatile("fence.proxy.async.shared::cta;" ::: "memory");
    }
    __syncthreads();

    const int nit = (NPLANES_TOTAL - bid + GRID - 1) / GRID;   // planes for this block

    // prologue: load plane 0 into stage 0
    if (tid == 0) {
        const float* src = feat + (size_t)bid * PLANE_ELEMS;
        asm volatile("mbarrier.arrive.expect_tx.shared.b64 _, [%0], %1;"
                     :: "r"(mb0), "r"((uint32_t)PLANE_BYTES) : "memory");
        asm volatile(
            "cp.async.bulk.shared::cta.global.mbarrier::complete_tx::bytes "
            "[%0], [%1], %2, [%3];"
            :: "r"(smem_u32(s_buf)), "l"(src), "r"((uint32_t)PLANE_BYTES), "r"(mb0)
            : "memory");
    }

    for (int i = 0; i < nit; i++) {
        const int stage = i & 1;
        const uint32_t mb = stage ? mb1 : mb0;

        // prefetch next plane into the other stage (free: its previous
        // compute finished before last iteration's __syncthreads)
        if (i + 1 < nit && tid == 0) {
            const int nstage = (i + 1) & 1;
            const uint32_t nmb = nstage ? mb1 : mb0;
            const float* src = feat + (size_t)(bid + (i + 1) * GRID) * PLANE_ELEMS;
            asm volatile("mbarrier.arrive.expect_tx.shared.b64 _, [%0], %1;"
                         :: "r"(nmb), "r"((uint32_t)PLANE_BYTES) : "memory");
            asm volatile(
                "cp.async.bulk.shared::cta.global.mbarrier::complete_tx::bytes "
                "[%0], [%1], %2, [%3];"
                :: "r"(smem_u32(s_buf + nstage * PLANE_ELEMS)), "l"(src),
                   "r"((uint32_t)PLANE_BYTES), "r"(nmb)
                : "memory");
        }

        // wait for current stage
        mbar_wait(mb, (i >> 1) & 1);

        const int plane = bid + i * GRID;
        const int b   = plane / NPLANE;
        const int idx = plane - b * NPLANE;          // co*49 + ph*7 + pw
        const int rem = idx % (PH * PW);
        const int ph  = rem / PW;
        const int pw  = rem - ph * PW;
        const float* sp = s_buf + stage * PLANE_ELEMS;

        const int off = g_boff[b];
        const int cnt = g_boff[b + 1] - off;
        const int nt  = cnt * 4;
        const int ntr = ((nt + TPB - 1) / TPB) * TPB;

        for (int t = tid; t < ntr; t += TPB) {
            const int g = t >> 2;                    // roi within batch list
            const int s = t & 3;                     // sample point
            const bool valid = g < cnt;
            const int slot = off + (valid ? g : cnt - 1);
            const int n = g_perm[slot];

            const float* p = g_params + (size_t)n * 4;
            const float x1 = __ldg(p + 0);
            const float y1 = __ldg(p + 1);
            const float bh = __ldg(p + 2);
            const float bw = __ldg(p + 3);

            const float fy = (s & 2) ? 0.75f : 0.25f;
            const float fx = (s & 1) ? 0.75f : 0.25f;
            const float y  = y1 + ((float)ph + fy) * bh;
            const float x  = x1 + ((float)pw + fx) * bw;

            // mask on UNCLIPPED coords (matches reference)
            const float m = (y >= -1.0f && y <= (float)HH &&
                             x >= -1.0f && x <= (float)WW) ? 1.0f : 0.0f;

            const float yc = fminf(fmaxf(y, 0.0f), (float)(HH - 1));
            const float xc = fminf(fmaxf(x, 0.0f), (float)(WW - 1));
            const int y0  = (int)yc;                 // yc >= 0 -> floor == trunc
            const int x0  = (int)xc;
            const int y1i = min(y0 + 1, HH - 1);
            const int x1i = min(x0 + 1, WW - 1);
            const float ly = yc - (float)y0, lx = xc - (float)x0;
            const float hy = 1.0f - ly,      hx = 1.0f - lx;

            const float* r0 = sp + y0  * WW;
            const float* r1 = sp + y1i * WW;
            const float v00 = r0[x0];
            const float v01 = r0[x1i];
            const float v10 = r1[x0];
            const float v11 = r1[x1i];

            float v = m * (hy * (hx * v00 + lx * v01) + ly * (hx * v10 + lx * v11));

            v += __shfl_xor_sync(0xffffffffu, v, 1);
            v += __shfl_xor_sync(0xffffffffu, v, 2);

            if (valid && s == 0)
                out[(size_t)n * NPLANE + idx] = v * (1.0f / (SR * SR));
        }

        // all threads done reading this stage before it is re-armed at i+2
        __syncthreads();
    }
}

extern "C" void kernel_launch(void* const* d_in, const int* in_sizes, int n_in,
                              void* d_out, int out_size) {
    const float* feat = (const float*)d_in[0];
    const float* rois = (const float*)d_in[1];
    float* out = (float*)d_out;
    cudaFuncSetAttribute(psroi_align_kernel,
                         cudaFuncAttributeMaxDynamicSharedMemorySize, SMEM_DYN);
    roi_prep_kernel<<<1, N_ROIS>>>(rois);
    psroi_align_kernel<<<GRID, TPB, SMEM_DYN>>>(feat, out);
}

// round 11
// speedup vs baseline: 1.0140x; 1.0140x over previous
#include <cuda_runtime.h>
#include <cstdint>

#define OUT_CH 16
#define PH 7
#define PW 7
#define SR 2
#define HH 80
#define WW 80
#define NPLANE (OUT_CH * PH * PW)        // 784 outputs per roi
#define N_ROIS 512
#define PARTS  8                         // blocks per roi
#define OPB    (NPLANE / PARTS)          // 98 outputs per block
#define TPB    (OPB * 4)                 // 392 threads (4 lanes per output)

// scratch (no allocation allowed)
__device__ float g_params[N_ROIS * 5];   // x1, y1, bh, bw, batch
__device__ int   g_perm[N_ROIS];         // rois sorted by batch index

// feat load with L2 evict_last residency policy: keeps the touched working
// set resident in L2 across graph replays.
__device__ __forceinline__ float ldg_resident(const float* p, uint64_t pol) {
    float v;
    asm("ld.global.nc.L2::cache_hint.f32 %0, [%1], %2;"
        : "=f"(v) : "l"(p), "l"(pol));
    return v;
}

// ── Kernel A: per-roi params + counting sort by batch (1 block) ──────────
__global__ void __launch_bounds__(N_ROIS)
roi_prep_kernel(const float* __restrict__ rois) {
    __shared__ int s_cnt[4];
    __shared__ int s_base[4];
    const int t = threadIdx.x;
    if (t < 4) s_cnt[t] = 0;
    __syncthreads();

    const float* r = rois + (size_t)t * 5;
    const int   b  = (int)r[0];
    const float x1 = r[1] * (float)WW;
    const float y1 = r[2] * (float)HH;
    const float x2 = r[3] * (float)WW;
    const float y2 = r[4] * (float)HH;
    float* p = g_params + (size_t)t * 5;
    p[0] = x1;
    p[1] = y1;
    p[2] = fmaxf(y2 - y1, 0.1f) * (1.0f / (float)PH);
    p[3] = fmaxf(x2 - x1, 0.1f) * (1.0f / (float)PW);
    p[4] = (float)b;

    const int rank = atomicAdd(&s_cnt[b], 1);
    __syncthreads();
    if (t == 0) {
        int acc = 0;
        for (int i = 0; i < 4; i++) { s_base[i] = acc; acc += s_cnt[i]; }
    }
    __syncthreads();
    g_perm[s_base[b] + rank] = t;
}

// ── Kernel B: main PSRoIAlign, batch-coherent block order ────────────────
__global__ void __launch_bounds__(TPB)
psroi_align_kernel(const float* __restrict__ feat,
                   float* __restrict__ out) {
    // evict_last policy for all feat traffic
    uint64_t pol;
    asm("createpolicy.fractional.L2::evict_last.b64 %0, 1.0;" : "=l"(pol));

    const int slot = blockIdx.x >> 3;         // sorted roi slot
    const int part = blockIdx.x & (PARTS - 1);
    const int n    = g_perm[slot];

    const float* p  = g_params + (size_t)n * 5;
    const float x1 = __ldg(p + 0);
    const float y1 = __ldg(p + 1);
    const float bh = __ldg(p + 2);
    const float bw = __ldg(p + 3);
    const int   b  = (int)__ldg(p + 4);

    const int q   = threadIdx.x >> 2;         // output within part (0..97)
    const int s   = threadIdx.x & 3;          // sample point (sy,sx)
    const int idx = part * OPB + q;           // channel = co*49 + ph*7 + pw
    const int rem = idx % (PH * PW);
    const int ph  = rem / PW;
    const int pw  = rem - ph * PW;

    const float fy = (s & 2) ? 0.75f : 0.25f;
    const float fx = (s & 1) ? 0.75f : 0.25f;
    const float y  = y1 + ((float)ph + fy) * bh;
    const float x  = x1 + ((float)pw + fx) * bw;

    // mask on UNCLIPPED coords (matches reference)
    const float m = (y >= -1.0f && y <= (float)HH &&
                     x >= -1.0f && x <= (float)WW) ? 1.0f : 0.0f;

    const float yc = fminf(fmaxf(y, 0.0f), (float)(HH - 1));
    const float xc = fminf(fmaxf(x, 0.0f), (float)(WW - 1));
    const int y0  = (int)yc;                  // yc >= 0 -> floor == trunc
    const int x0  = (int)xc;
    const int y1i = min(y0 + 1, HH - 1);
    const int x1i = min(x0 + 1, WW - 1);
    const float ly = yc - (float)y0, lx = xc - (float)x0;
    const float hy = 1.0f - ly,      hx = 1.0f - lx;

    const float* plane = feat + ((size_t)b * NPLANE + (size_t)idx) * (HH * WW);
    const float* r0 = plane + y0  * WW;
    const float* r1 = plane + y1i * WW;
    const float v00 = ldg_resident(r0 + x0,  pol);
    const float v01 = ldg_resident(r0 + x1i, pol);
    const float v10 = ldg_resident(r1 + x0,  pol);
    const float v11 = ldg_resident(r1 + x1i, pol);

    float v = m * (hy * (hx * v00 + lx * v01) + ly * (hx * v10 + lx * v11));

    // reduce the 4 sample points (lanes s=0..3) of this output
    v += __shfl_xor_sync(0xffffffffu, v, 1);
    v += __shfl_xor_sync(0xffffffffu, v, 2);

    if (s == 0) out[(size_t)n * NPLANE + idx] = v * (1.0f / (SR * SR));
}

extern "C" void kernel_launch(void* const* d_in, const int* in_sizes, int n_in,
                              void* d_out, int out_size) {
    const float* feat = (const float*)d_in[0];
    const float* rois = (const float*)d_in[1];
    float* out = (float*)d_out;
    roi_prep_kernel<<<1, N_ROIS>>>(rois);
    psroi_align_kernel<<<N_ROIS * PARTS, TPB>>>(feat, out);
}

// round 13
// speedup vs baseline: 1.0920x; 1.0769x over previous
#include <cuda_runtime.h>
#include <cstdint>

#define OUT_CH 16
#define PH 7
#define PW 7
#define SR 2
#define HH 80
#define WW 80
#define PLANE_ELEMS (HH * WW)            // 6400 floats
#define PLANE_BYTES (PLANE_ELEMS * 4)    // 25600 B
#define NPLANE (OUT_CH * PH * PW)        // 784 channels per batch
#define N_ROIS 512
#define NB 4
#define NPLANES_TOTAL (NB * NPLANE)      // 3136
#define TPB 512
#define GRID 296                          // 2 persistent blocks per SM
#define NSTAGES 4
#define SMEM_DYN (NSTAGES * PLANE_BYTES)  // 102400 B

// scratch (no allocation allowed)
__device__ float g_params[N_ROIS * 4];    // x1, y1, bh, bw
__device__ int   g_perm[N_ROIS];          // rois sorted by batch
__device__ int   g_boff[NB + 1];          // batch list offsets

__device__ __forceinline__ uint32_t smem_u32(const void* p) {
    uint32_t a;
    asm("{ .reg .u64 t; cvta.to.shared.u64 t, %1; cvt.u32.u64 %0, t; }"
        : "=r"(a) : "l"(p));
    return a;
}

__device__ __forceinline__ void mbar_wait(uint32_t mbar, uint32_t parity) {
    uint32_t done;
    asm volatile(
        "{\n\t.reg .pred p;\n\t"
        "mbarrier.try_wait.parity.acquire.cta.shared::cta.b64 p, [%1], %2;\n\t"
        "selp.b32 %0, 1, 0, p;\n\t}"
        : "=r"(done) : "r"(mbar), "r"(parity) : "memory");
    if (!done) {
        asm volatile(
            "{\n\t.reg .pred P1;\n\t"
            "WAIT_LOOP_%=:\n\t"
            "mbarrier.try_wait.parity.acquire.cta.shared::cta.b64 P1, [%0], %1, 0x989680;\n\t"
            "@P1 bra.uni WAIT_DONE_%=;\n\t"
            "bra.uni WAIT_LOOP_%=;\n\t"
            "WAIT_DONE_%=:\n\t}"
            :: "r"(mbar), "r"(parity) : "memory");
    }
}

// ── Kernel A: per-roi params + counting sort by batch ───────────────────
__global__ void __launch_bounds__(N_ROIS)
roi_prep_kernel(const float* __restrict__ rois) {
    __shared__ int s_cnt[NB];
    __shared__ int s_base[NB];
    const int t = threadIdx.x;
    if (t < NB) s_cnt[t] = 0;
    __syncthreads();

    const float* r = rois + (size_t)t * 5;
    const int   b  = (int)r[0];
    const float x1 = r[1] * (float)WW;
    const float y1 = r[2] * (float)HH;
    const float x2 = r[3] * (float)WW;
    const float y2 = r[4] * (float)HH;
    float* p = g_params + (size_t)t * 4;
    p[0] = x1;
    p[1] = y1;
    p[2] = fmaxf(y2 - y1, 0.1f) * (1.0f / (float)PH);
    p[3] = fmaxf(x2 - x1, 0.1f) * (1.0f / (float)PW);

    const int rank = atomicAdd(&s_cnt[b], 1);
    __syncthreads();
    if (t == 0) {
        int acc = 0;
        for (int i = 0; i < NB; i++) { s_base[i] = acc; g_boff[i] = acc; acc += s_cnt[i]; }
        g_boff[NB] = acc;
    }
    __syncthreads();
    g_perm[s_base[b] + rank] = t;
}

// ── Kernel B: persistent blocks, 4-stage TMA pipeline ───────────────────
__global__ void __launch_bounds__(TPB)
psroi_align_kernel(const float* __restrict__ feat,
                   float* __restrict__ out) {
    extern __shared__ __align__(16) float s_buf[];      // [NSTAGES][PLANE_ELEMS]
    __shared__ alignas(8) uint64_t s_mbar[NSTAGES];

    const int tid = threadIdx.x;
    const int bid = blockIdx.x;

    if (tid == 0) {
        #pragma unroll
        for (int j = 0; j < NSTAGES; j++)
            asm volatile("mbarrier.init.shared.b64 [%0], 1;"
                         :: "r"(smem_u32(&s_mbar[j])) : "memory");
        asm volatile("fence.proxy.async.shared::cta;" ::: "memory");
    }
    __syncthreads();

    const int nit = (NPLANES_TOTAL - bid + GRID - 1) / GRID;   // planes for this block

    // prologue: fill first NSTAGES-1 stages
    if (tid == 0) {
        #pragma unroll
        for (int j = 0; j < NSTAGES - 1; j++) {
            if (j < nit) {
                const uint32_t mb = smem_u32(&s_mbar[j]);
                const float* src = feat + (size_t)(bid + j * GRID) * PLANE_ELEMS;
                asm volatile("mbarrier.arrive.expect_tx.shared.b64 _, [%0], %1;"
                             :: "r"(mb), "r"((uint32_t)PLANE_BYTES) : "memory");
                asm volatile(
                    "cp.async.bulk.shared::cta.global.mbarrier::complete_tx::bytes "
                    "[%0], [%1], %2, [%3];"
                    :: "r"(smem_u32(s_buf + j * PLANE_ELEMS)), "l"(src),
                       "r"((uint32_t)PLANE_BYTES), "r"(mb)
                    : "memory");
            }
        }
    }

    for (int i = 0; i < nit; i++) {
        const int stage = i & (NSTAGES - 1);
        const uint32_t mb = smem_u32(&s_mbar[stage]);

        // issue the load NSTAGES-1 ahead: its buffer was consumed at i-1 and
        // the trailing __syncthreads of i-1 ordered all reads before this.
        const int pre = i + NSTAGES - 1;
        if (pre < nit && tid == 0) {
            const int pstage = pre & (NSTAGES - 1);
            const uint32_t pmb = smem_u32(&s_mbar[pstage]);
            const float* src = feat + (size_t)(bid + pre * GRID) * PLANE_ELEMS;
            asm volatile("mbarrier.arrive.expect_tx.shared.b64 _, [%0], %1;"
                         :: "r"(pmb), "r"((uint32_t)PLANE_BYTES) : "memory");
            asm volatile(
                "cp.async.bulk.shared::cta.global.mbarrier::complete_tx::bytes "
                "[%0], [%1], %2, [%3];"
                :: "r"(smem_u32(s_buf + pstage * PLANE_ELEMS)), "l"(src),
                   "r"((uint32_t)PLANE_BYTES), "r"(pmb)
                : "memory");
        }

        // wait for current stage (use-count parity: use k of a stage -> k&1)
        mbar_wait(mb, (i >> 2) & 1);

        const int plane = bid + i * GRID;
        const int b   = plane / NPLANE;
        const int idx = plane - b * NPLANE;          // co*49 + ph*7 + pw
        const int rem = idx % (PH * PW);
        const int ph  = rem / PW;
        const int pw  = rem - ph * PW;
        const float* sp = s_buf + stage * PLANE_ELEMS;

        const int off = g_boff[b];
        const int cnt = g_boff[b + 1] - off;
        const int nt  = cnt * 4;
        const int ntr = ((nt + TPB - 1) / TPB) * TPB;   // full warps in loop

        for (int t = tid; t < ntr; t += TPB) {
            const int g = t >> 2;                    // roi within batch list
            const int s = t & 3;                     // sample point
            const bool valid = g < cnt;
            const int n = g_perm[off + (valid ? g : cnt - 1)];

            const float* p = g_params + (size_t)n * 4;
            const float x1 = __ldg(p + 0);
            const float y1 = __ldg(p + 1);
            const float bh = __ldg(p + 2);
            const float bw = __ldg(p + 3);

            const float fy = (s & 2) ? 0.75f : 0.25f;
            const float fx = (s & 1) ? 0.75f : 0.25f;
            const float y  = y1 + ((float)ph + fy) * bh;
            const float x  = x1 + ((float)pw + fx) * bw;

            // mask on UNCLIPPED coords (matches reference)
            const float m = (y >= -1.0f && y <= (float)HH &&
                             x >= -1.0f && x <= (float)WW) ? 1.0f : 0.0f;

            const float yc = fminf(fmaxf(y, 0.0f), (float)(HH - 1));
            const float xc = fminf(fmaxf(x, 0.0f), (float)(WW - 1));
            const int y0  = (int)yc;                 // yc >= 0 -> floor == trunc
            const int x0  = (int)xc;
            const int y1i = min(y0 + 1, HH - 1);
            const int x1i = min(x0 + 1, WW - 1);
            const float ly = yc - (float)y0, lx = xc - (float)x0;
            const float hy = 1.0f - ly,      hx = 1.0f - lx;

            const float* r0 = sp + y0  * WW;
            const float* r1 = sp + y1i * WW;
            const float v00 = r0[x0];
            const float v01 = r0[x1i];
            const float v10 = r1[x0];
            const float v11 = r1[x1i];

            float v = m * (hy * (hx * v00 + lx * v01) + ly * (hx * v10 + lx * v11));

            // lanes s=0..3 of one output are adjacent; whole warp active here
            v += __shfl_xor_sync(0xffffffffu, v, 1);
            v += __shfl_xor_sync(0xffffffffu, v, 2);

            if (valid && s == 0)
                out[(size_t)n * NPLANE + idx] = v * (1.0f / (SR * SR));
        }

        // all threads done reading this stage before it is re-armed
        __syncthreads();
    }
}

extern "C" void kernel_launch(void* const* d_in, const int* in_sizes, int n_in,
                              void* d_out, int out_size) {
    const float* feat = (const float*)d_in[0];
    const float* rois = (const float*)d_in[1];
    float* out = (float*)d_out;
    cudaFuncSetAttribute(psroi_align_kernel,
                         cudaFuncAttributeMaxDynamicSharedMemorySize, SMEM_DYN);
    roi_prep_kernel<<<1, N_ROIS>>>(rois);
    psroi_align_kernel<<<GRID, TPB, SMEM_DYN>>>(feat, out);
}

// round 14
// speedup vs baseline: 1.3250x; 1.2133x over previous
#include <cuda_runtime.h>
#include <cstdint>

#define OUT_CH 16
#define PH 7
#define PW 7
#define SR 2
#define HH 80
#define WW 80
#define PLANE_ELEMS (HH * WW)            // 6400 floats
#define NPLANE (OUT_CH * PH * PW)        // 784 channels per batch
#define N_ROIS 512
#define NB 4
#define NPLANES_TOTAL (NB * NPLANE)      // 3136 blocks
#define TPB 512

// scratch (no allocation allowed)
__device__ __align__(16) float g_params[N_ROIS * 4];  // x1, y1, bh, bw
__device__ int g_perm[N_ROIS];            // rois sorted by batch
__device__ int g_boff[NB + 1];            // batch list offsets

// ── Kernel A: per-roi params + counting sort by batch ───────────────────
__global__ void __launch_bounds__(N_ROIS)
roi_prep_kernel(const float* __restrict__ rois) {
    __shared__ int s_cnt[NB];
    __shared__ int s_base[NB];
    const int t = threadIdx.x;
    if (t < NB) s_cnt[t] = 0;
    __syncthreads();

    const float* r = rois + (size_t)t * 5;
    const int   b  = (int)r[0];
    const float x1 = r[1] * (float)WW;
    const float y1 = r[2] * (float)HH;
    const float x2 = r[3] * (float)WW;
    const float y2 = r[4] * (float)HH;
    float* p = g_params + (size_t)t * 4;
    p[0] = x1;
    p[1] = y1;
    p[2] = fmaxf(y2 - y1, 0.1f) * (1.0f / (float)PH);
    p[3] = fmaxf(x2 - x1, 0.1f) * (1.0f / (float)PW);

    const int rank = atomicAdd(&s_cnt[b], 1);
    __syncthreads();
    if (t == 0) {
        int acc = 0;
        for (int i = 0; i < NB; i++) { s_base[i] = acc; g_boff[i] = acc; acc += s_cnt[i]; }
        g_boff[NB] = acc;
    }
    __syncthreads();
    g_perm[s_base[b] + rank] = t;
}

// ── Kernel B: one block per plane; direct global gather, all rois ───────
__global__ void __launch_bounds__(TPB)
psroi_align_kernel(const float* __restrict__ feat,
                   float* __restrict__ out) {
    const int plane = blockIdx.x;                 // batch-major plane order
    const int b   = plane / NPLANE;
    const int idx = plane - b * NPLANE;           // channel = co*49 + ph*7 + pw
    const int rem = idx % (PH * PW);
    const int ph  = rem / PW;
    const int pw  = rem - ph * PW;
    const int tid = threadIdx.x;

    const float* __restrict__ fp = feat + (size_t)plane * PLANE_ELEMS;

    const int off = g_boff[b];
    const int cnt = g_boff[b + 1] - off;
    const int nt  = cnt * 4;
    const int ntr = ((nt + TPB - 1) / TPB) * TPB;   // full warps in loop

    for (int t = tid; t < ntr; t += TPB) {
        const int g = t >> 2;                     // roi within batch list
        const int s = t & 3;                      // sample point (sy,sx)
        const bool valid = g < cnt;
        const int n = g_perm[off + (valid ? g : cnt - 1)];

        const float4 prm = *(const float4*)(g_params + (size_t)n * 4);
        const float x1 = prm.x;
        const float y1 = prm.y;
        const float bh = prm.z;
        const float bw = prm.w;

        const float fy = (s & 2) ? 0.75f : 0.25f;
        const float fx = (s & 1) ? 0.75f : 0.25f;
        const float y  = y1 + ((float)ph + fy) * bh;
        const float x  = x1 + ((float)pw + fx) * bw;

        // mask on UNCLIPPED coords (matches reference)
        const float m = (y >= -1.0f && y <= (float)HH &&
                         x >= -1.0f && x <= (float)WW) ? 1.0f : 0.0f;

        const float yc = fminf(fmaxf(y, 0.0f), (float)(HH - 1));
        const float xc = fminf(fmaxf(x, 0.0f), (float)(WW - 1));
        const int y0  = (int)yc;                  // yc >= 0 -> floor == trunc
        const int x0  = (int)xc;
        const int y1i = min(y0 + 1, HH - 1);
        const int x1i = min(x0 + 1, WW - 1);
        const float ly = yc - (float)y0, lx = xc - (float)x0;
        const float hy = 1.0f - ly,      hx = 1.0f - lx;

        const float* r0 = fp + y0  * WW;
        const float* r1 = fp + y1i * WW;
        const float v00 = __ldg(r0 + x0);
        const float v01 = __ldg(r0 + x1i);
        const float v10 = __ldg(r1 + x0);
        const float v11 = __ldg(r1 + x1i);

        float v = m * (hy * (hx * v00 + lx * v01) + ly * (hx * v10 + lx * v11));

        // lanes s=0..3 of one output are adjacent; whole warp active here
        v += __shfl_xor_sync(0xffffffffu, v, 1);
        v += __shfl_xor_sync(0xffffffffu, v, 2);

        if (valid && s == 0)
            out[(size_t)n * NPLANE + idx] = v * (1.0f / (SR * SR));
    }
}

extern "C" void kernel_launch(void* const* d_in, const int* in_sizes, int n_in,
                              void* d_out, int out_size) {
    const float* feat = (const float*)d_in[0];
    const float* rois = (const float*)d_in[1];
    float* out = (float*)d_out;
    roi_prep_kernel<<<1, N_ROIS>>>(rois);
    psroi_align_kernel<<<NPLANES_TOTAL, TPB>>>(feat, out);
}